// round 16
// baseline (speedup 1.0000x reference)
#include <cuda_runtime.h>
#include <cuda_fp16.h>
#include <mma.h>
#include <cstdint>

using namespace nvcuda;

// Problem dims
#define DIM_B    16
#define DIM_K    8
#define DIM_N    196
#define DIM_D    768
#define DIM_H    3072
#define DIM_DOUT 768

#define M2      (DIM_B * DIM_N)   // 3136
#define M2_PAD  3200              // 25*128
#define MSP     324
#define MSP_PAD 384

// Scratch (zero-initialized at module load; padded rows of g_Gh stay 0)
__device__ __half g_Ah[MSP_PAD * DIM_D];     // fp16 [slots;pos] (GEMM1 A)
__device__ __half g_W1h[DIM_D * DIM_H];      // fp16 W1 (GEMM1 B)
__device__ float  g_SP1[MSP_PAD * DIM_H];    // fp32: slots@W1 (0..127), pos@W1 (128..323)
__device__ __half g_Gh[M2_PAD * DIM_H];      // fp16 combined hidden (GEMM2 A)
__device__ __half g_W2h[DIM_H * DIM_DOUT];   // fp16 W2 (GEMM2 B)

// ---------------------------------------------------------------------------
// helpers
// ---------------------------------------------------------------------------
__device__ __forceinline__ void cp16u(unsigned saddr, const void* g) {
    asm volatile("cp.async.cg.shared.global [%0], [%1], 16;"
                 :: "r"(saddr), "l"(g));
}
__device__ __forceinline__ unsigned smem_u32(const void* p) {
    unsigned a;
    asm("{ .reg .u64 t; cvta.to.shared.u64 t, %1; cvt.u32.u64 %0, t; }"
        : "=r"(a) : "l"(p));
    return a;
}
__device__ __forceinline__ uint2 f4_to_h4(float4 v) {
    __half2 h01 = __floats2half2_rn(v.x, v.y);
    __half2 h23 = __floats2half2_rn(v.z, v.w);
    uint2 u;
    u.x = *(unsigned*)&h01;
    u.y = *(unsigned*)&h23;
    return u;
}

// ---------------------------------------------------------------------------
// Kernel 0: fp16 conversion of W1 and [slots;pos]
// ---------------------------------------------------------------------------
#define W1_F4 (DIM_D * DIM_H / 4)
#define W2_F4 (DIM_H * DIM_DOUT / 4)
#define A_F4  (MSP_PAD * DIM_D / 4)

__global__ __launch_bounds__(256) void conv_kernel(
    const float* __restrict__ W1,
    const float* __restrict__ slots,
    const float* __restrict__ pos)
{
    int i = blockIdx.x * 256 + threadIdx.x;
    if (i < W1_F4) {
        *(uint2*)&g_W1h[i * 4] = f4_to_h4(*(const float4*)&W1[i * 4]);
    } else if (i < W1_F4 + A_F4) {
        int j = i - W1_F4;
        int m = (j * 4) / DIM_D;
        int c = (j * 4) % DIM_D;
        float4 v = make_float4(0.f, 0.f, 0.f, 0.f);
        if (m < 128)      v = *(const float4*)&slots[m * DIM_D + c];
        else if (m < MSP) v = *(const float4*)&pos[(m - 128) * DIM_D + c];
        *(uint2*)&g_Ah[j * 4] = f4_to_h4(v);
    }
}

#define LDA 72     // halves (64 + 8 pad)
#define LDB 136    // halves (128 + 8 pad)
#define ASZ (64 * LDA)          // halves per 64-row A stage
#define BSZ (64 * LDB)          // halves per B stage

// ---------------------------------------------------------------------------
// Kernel 1: GEMM1  g_Ah(384x768) @ g_W1h(768x3072) -> g_SP1 (fp32)
// BM=64 BN=128 BK=64, 256 thr, warp 32x32, 4-stage pipeline. grid (24,6)
// ---------------------------------------------------------------------------
#define G1_NSTG 4
#define G1_SMEM (G1_NSTG * (ASZ + BSZ) * 2)   // 106496

__global__ __launch_bounds__(256) void gemm_small_kernel()
{
    constexpr int KT = DIM_D / 64;   // 12

    extern __shared__ __align__(16) char smraw[];
    __half* As = (__half*)smraw;
    __half* Bs = As + G1_NSTG * ASZ;
    const unsigned sb  = smem_u32(smraw);
    const unsigned sbB = sb + G1_NSTG * ASZ * 2;

    const int h0  = blockIdx.x * 128;
    const int m0  = blockIdx.y * 64;
    const int tid = threadIdx.x;
    const int wid = tid >> 5;
    const int warp_m = wid >> 2;
    const int warp_n = wid & 3;

    wmma::fragment<wmma::accumulator, 16, 16, 16, float> acc[2][2];
#pragma unroll
    for (int i = 0; i < 2; i++)
#pragma unroll
        for (int j = 0; j < 2; j++)
            wmma::fill_fragment(acc[i][j], 0.0f);

    const int ar = tid >> 2, ac = (tid & 3) * 8;
    const int br = tid >> 4, bc = (tid & 15) * 8;

    const __half* gA = g_Ah + (size_t)(m0 + ar) * DIM_D + ac;

#define LOAD1(kt, st)                                                             \
    {                                                                             \
        unsigned sA0 = sb + (st) * ASZ * 2;                                       \
        cp16u(sA0 + (ar * LDA + ac) * 2,        gA + (kt) * 64);                  \
        cp16u(sA0 + (ar * LDA + ac + 32) * 2,   gA + (kt) * 64 + 32);             \
        const __half* gB = g_W1h + (size_t)((kt) * 64 + br) * DIM_H + h0 + bc;    \
        unsigned sB0 = sbB + (st) * BSZ * 2;                                      \
        cp16u(sB0 + (br * LDB + bc) * 2,        gB);                              \
        cp16u(sB0 + ((br + 16) * LDB + bc) * 2, gB + (size_t)16 * DIM_H);         \
        cp16u(sB0 + ((br + 32) * LDB + bc) * 2, gB + (size_t)32 * DIM_H);         \
        cp16u(sB0 + ((br + 48) * LDB + bc) * 2, gB + (size_t)48 * DIM_H);         \
    }

#pragma unroll
    for (int p = 0; p < G1_NSTG - 1; p++) {
        LOAD1(p, p);
        asm volatile("cp.async.commit_group;");
    }

    for (int kt = 0; kt < KT; kt++) {
        asm volatile("cp.async.wait_group %0;" :: "n"(G1_NSTG - 2));
        __syncthreads();
        if (kt + G1_NSTG - 1 < KT) {
            LOAD1(kt + G1_NSTG - 1, (kt + G1_NSTG - 1) & (G1_NSTG - 1));
        }
        asm volatile("cp.async.commit_group;");
        const __half* sA = As + (kt & (G1_NSTG - 1)) * ASZ;
        const __half* sB = Bs + (kt & (G1_NSTG - 1)) * BSZ;
#pragma unroll
        for (int ks = 0; ks < 64; ks += 16) {
            wmma::fragment<wmma::matrix_a, 16, 16, 16, __half, wmma::row_major> af[2];
            wmma::fragment<wmma::matrix_b, 16, 16, 16, __half, wmma::row_major> bf[2];
#pragma unroll
            for (int i = 0; i < 2; i++)
                wmma::load_matrix_sync(af[i], &sA[(warp_m * 32 + i * 16) * LDA + ks], LDA);
#pragma unroll
            for (int j = 0; j < 2; j++)
                wmma::load_matrix_sync(bf[j], &sB[ks * LDB + warp_n * 32 + j * 16], LDB);
#pragma unroll
            for (int i = 0; i < 2; i++)
#pragma unroll
                for (int j = 0; j < 2; j++)
                    wmma::mma_sync(acc[i][j], af[i], bf[j], acc[i][j]);
        }
    }
#undef LOAD1

#pragma unroll
    for (int i = 0; i < 2; i++)
#pragma unroll
        for (int j = 0; j < 2; j++)
            wmma::store_matrix_sync(
                &g_SP1[(size_t)(m0 + warp_m * 32 + i * 16) * DIM_H + h0 + warp_n * 32 + j * 16],
                acc[i][j], DIM_H, wmma::mem_row_major);
}

// ---------------------------------------------------------------------------
// Kernel 2: combine (z<16) + W2->fp16 conversion (z==16). grid (14,3,17)
// ---------------------------------------------------------------------------
__global__ __launch_bounds__(256) void combine_kernel(
    const float* __restrict__ b1,
    const float* __restrict__ W2)
{
    if (blockIdx.z == 16) {
        int base = (blockIdx.y * 14 + blockIdx.x) * 256 + threadIdx.x;
        for (int i = base; i < W2_F4; i += 42 * 256) {
            *(uint2*)&g_W2h[i * 4] = f4_to_h4(*(const float4*)&W2[i * 4]);
        }
        return;
    }

    const int b  = blockIdx.z;
    const int h0 = blockIdx.y * 1024 + threadIdx.x * 4;
    const int n0 = blockIdx.x * 14;

    float4 s[8];
#pragma unroll
    for (int k = 0; k < 8; k++)
        s[k] = *(const float4*)&g_SP1[(size_t)(b * 8 + k) * DIM_H + h0];
    float4 bb = *(const float4*)&b1[h0];
#pragma unroll
    for (int k = 0; k < 8; k++) {
        s[k].x += bb.x; s[k].y += bb.y; s[k].z += bb.z; s[k].w += bb.w;
    }

#pragma unroll 2
    for (int n = 0; n < 14; n++) {
        int nn = n0 + n;
        float4 p = *(const float4*)&g_SP1[(size_t)(128 + nn) * DIM_H + h0];
        float4 a;
        a.x = a.y = a.z = a.w = 0.0f;
#pragma unroll
        for (int k = 0; k < 8; k++) {
            a.x += fmaxf(s[k].x + p.x, 0.0f);
            a.y += fmaxf(s[k].y + p.y, 0.0f);
            a.z += fmaxf(s[k].z + p.z, 0.0f);
            a.w += fmaxf(s[k].w + p.w, 0.0f);
        }
        a.x *= 0.125f; a.y *= 0.125f; a.z *= 0.125f; a.w *= 0.125f;
        *(uint2*)&g_Gh[(size_t)(b * DIM_N + nn) * DIM_H + h0] = f4_to_h4(a);
    }
}

// ---------------------------------------------------------------------------
// Pass 2 (fp16): out(3136x768) = Gh(3200x3072) @ W2h(3072x768) + b2
// BM=128 BN=128 BK=64, 256 thr (warp tile 64x32, acc 4x2), NSTG=2 double
// buffer (71.7KB smem -> 2 CTAs/SM), grid (6,25)=150 all-resident.
// L2 traffic 233MB vs 351MB at BM=64.
// ---------------------------------------------------------------------------
#define P2_ASZ (128 * LDA)    // 9216 halves
#define P2_BSZ (64 * LDB)     // 8704 halves
#define P2_SMEM (2 * (P2_ASZ + P2_BSZ) * 2)   // 71680

__global__ __launch_bounds__(256, 2) void pass2_kernel(
    const float* __restrict__ b2,
    float* __restrict__ out)
{
    constexpr int KT  = DIM_H / 64;   // 48
    constexpr int LDC = 132;          // floats

    extern __shared__ __align__(16) char smraw[];
    __half* As = (__half*)smraw;             // 2 * P2_ASZ
    __half* Bs = As + 2 * P2_ASZ;            // 2 * P2_BSZ
    float*  Cs = (float*)smraw;              // epilogue: 128*132*4 = 67584 B

    const unsigned sb  = smem_u32(smraw);
    const unsigned sbB = sb + 2 * P2_ASZ * 2;

    const int o0  = blockIdx.x * 128;
    const int m0  = blockIdx.y * 128;
    const int tid = threadIdx.x;
    const int wid = tid >> 5;
    const int warp_m = wid >> 2;   // 0..1 -> 64 rows
    const int warp_n = wid & 3;    // 0..3 -> 32 cols

    wmma::fragment<wmma::accumulator, 16, 16, 16, float> acc[4][2];
#pragma unroll
    for (int i = 0; i < 4; i++)
#pragma unroll
        for (int j = 0; j < 2; j++)
            wmma::fill_fragment(acc[i][j], 0.0f);

    // A: 128 rows x 64 halves (128B/row) = 1024 cp16, 4/thread: 2 thr/row
    const int ar = tid >> 1, ac = (tid & 1) * 32;
    // B: 64 rows x 128 halves = 1024 cp16, 4/thread (rows +16)
    const int br = tid >> 4, bc = (tid & 15) * 8;

    const __half* gA = g_Gh + (size_t)(m0 + ar) * DIM_H + ac;

#define LOAD2(kt, st)                                                             \
    {                                                                             \
        unsigned sA0 = sb + (st) * P2_ASZ * 2 + (ar * LDA + ac) * 2;              \
        const __half* a_ = gA + (kt) * 64;                                        \
        cp16u(sA0,      a_);                                                      \
        cp16u(sA0 + 16, a_ + 8);                                                  \
        cp16u(sA0 + 32, a_ + 16);                                                 \
        cp16u(sA0 + 48, a_ + 24);                                                 \
        const __half* gB = g_W2h + (size_t)((kt) * 64 + br) * DIM_DOUT + o0 + bc; \
        unsigned sB0 = sbB + (st) * P2_BSZ * 2;                                   \
        cp16u(sB0 + (br * LDB + bc) * 2,        gB);                              \
        cp16u(sB0 + ((br + 16) * LDB + bc) * 2, gB + 16 * DIM_DOUT);              \
        cp16u(sB0 + ((br + 32) * LDB + bc) * 2, gB + 32 * DIM_DOUT);              \
        cp16u(sB0 + ((br + 48) * LDB + bc) * 2, gB + 48 * DIM_DOUT);              \
    }

    LOAD2(0, 0);
    asm volatile("cp.async.commit_group;");

    for (int kt = 0; kt < KT; kt++) {
        asm volatile("cp.async.wait_group 0;");
        __syncthreads();
        if (kt + 1 < KT) {
            LOAD2(kt + 1, (kt + 1) & 1);
            asm volatile("cp.async.commit_group;");
        }
        const __half* sA = As + (kt & 1) * P2_ASZ;
        const __half* sB = Bs + (kt & 1) * P2_BSZ;
#pragma unroll
        for (int ks = 0; ks < 64; ks += 16) {
            wmma::fragment<wmma::matrix_a, 16, 16, 16, __half, wmma::row_major> af[4];
            wmma::fragment<wmma::matrix_b, 16, 16, 16, __half, wmma::row_major> bf[2];
#pragma unroll
            for (int i = 0; i < 4; i++)
                wmma::load_matrix_sync(af[i], &sA[(warp_m * 64 + i * 16) * LDA + ks], LDA);
#pragma unroll
            for (int j = 0; j < 2; j++)
                wmma::load_matrix_sync(bf[j], &sB[ks * LDB + warp_n * 32 + j * 16], LDB);
#pragma unroll
            for (int i = 0; i < 4; i++)
#pragma unroll
                for (int j = 0; j < 2; j++)
                    wmma::mma_sync(acc[i][j], af[i], bf[j], acc[i][j]);
        }
        __syncthreads();
    }
#undef LOAD2

    // epilogue via smem (reuses tile space), add bias, write out
#pragma unroll
    for (int i = 0; i < 4; i++)
#pragma unroll
        for (int j = 0; j < 2; j++)
            wmma::store_matrix_sync(
                &Cs[(warp_m * 64 + i * 16) * LDC + warp_n * 32 + j * 16],
                acc[i][j], LDC, wmma::mem_row_major);
    __syncthreads();

    // 128 rows x 32 float4 = 4096 slots -> 16 iterations (guard padded rows)
#pragma unroll
    for (int p = 0; p < 16; p++) {
        int o = p * 256 + tid;
        int r = o >> 5, c4 = (o & 31) * 4;
        int m = m0 + r;
        if (m < M2) {
            float4 v = *(float4*)&Cs[r * LDC + c4];
            float4 bb = *(const float4*)&b2[o0 + c4];
            v.x += bb.x; v.y += bb.y; v.z += bb.z; v.w += bb.w;
            *(float4*)&out[(size_t)m * DIM_DOUT + o0 + c4] = v;
        }
    }
}

// ---------------------------------------------------------------------------
extern "C" void kernel_launch(void* const* d_in, const int* in_sizes, int n_in,
                              void* d_out, int out_size)
{
    const float* slots = (const float*)d_in[0];   // (16,8,768)
    const float* pos   = (const float*)d_in[1];   // (196,768)
    // d_in[2] = map_alpha : softmax over K of identical values == 1/8 exactly
    const float* W1    = (const float*)d_in[3];   // (768,3072)
    const float* b1    = (const float*)d_in[4];   // (3072,)
    const float* W2    = (const float*)d_in[5];   // (3072,768)
    const float* b2    = (const float*)d_in[6];   // (768,)
    float* out = (float*)d_out;                   // (16,196,768)

    cudaFuncSetAttribute(gemm_small_kernel,
                         cudaFuncAttributeMaxDynamicSharedMemorySize, G1_SMEM);
    cudaFuncSetAttribute(pass2_kernel,
                         cudaFuncAttributeMaxDynamicSharedMemorySize, P2_SMEM);

    constexpr int CONV_BLKS = (W1_F4 + A_F4 + 255) / 256;
    conv_kernel<<<CONV_BLKS, 256>>>(W1, slots, pos);

    dim3 gs(DIM_H / 128, MSP_PAD / 64);             // (24, 6)
    gemm_small_kernel<<<gs, 256, G1_SMEM>>>();

    dim3 gc(14, 3, 17);                             // combine + W2 conversion
    combine_kernel<<<gc, 256>>>(b1, W2);

    dim3 g2(DIM_DOUT / 128, M2_PAD / 128);          // (6, 25) = 150 blocks
    pass2_kernel<<<g2, 256, P2_SMEM>>>(b2, out);
}

// round 17
// speedup vs baseline: 1.0705x; 1.0705x over previous
#include <cuda_runtime.h>
#include <cuda_fp16.h>
#include <mma.h>
#include <cstdint>

using namespace nvcuda;

// Problem dims
#define DIM_B    16
#define DIM_K    8
#define DIM_N    196
#define DIM_D    768
#define DIM_H    3072
#define DIM_DOUT 768

#define M2      (DIM_B * DIM_N)   // 3136 = 49*64 exactly
#define MSP     324               // 128 slot rows + 196 pos rows
#define MSP_PAD 384

// Scratch (zero-initialized at module load)
__device__ __half g_Ah[MSP_PAD * DIM_D];     // fp16 [slots;pos] (GEMM1 A)
__device__ __half g_W1h[DIM_D * DIM_H];      // fp16 W1 (GEMM1 B)
__device__ __half g_SP1h[MSP_PAD * DIM_H];   // fp16: slots@W1 (0..127), pos@W1 (128..323)
__device__ __half g_Gh[M2 * DIM_H];          // fp16 combined hidden (GEMM2 A)
__device__ __half g_W2h[DIM_H * DIM_DOUT];   // fp16 W2 (GEMM2 B)

// ---------------------------------------------------------------------------
// helpers
// ---------------------------------------------------------------------------
__device__ __forceinline__ void cp16u(unsigned saddr, const void* g) {
    asm volatile("cp.async.cg.shared.global [%0], [%1], 16;"
                 :: "r"(saddr), "l"(g));
}
__device__ __forceinline__ unsigned smem_u32(const void* p) {
    unsigned a;
    asm("{ .reg .u64 t; cvta.to.shared.u64 t, %1; cvt.u32.u64 %0, t; }"
        : "=r"(a) : "l"(p));
    return a;
}
__device__ __forceinline__ uint2 f4_to_h4(float4 v) {
    __half2 h01 = __floats2half2_rn(v.x, v.y);
    __half2 h23 = __floats2half2_rn(v.z, v.w);
    uint2 u;
    u.x = *(unsigned*)&h01;
    u.y = *(unsigned*)&h23;
    return u;
}
__device__ __forceinline__ float4 h4_to_f4(uint2 u) {
    float2 f01 = __half22float2(*(__half2*)&u.x);
    float2 f23 = __half22float2(*(__half2*)&u.y);
    return make_float4(f01.x, f01.y, f23.x, f23.y);
}

// ---------------------------------------------------------------------------
// Kernel 0: fp16 conversion of W1 and [slots;pos]
// ---------------------------------------------------------------------------
#define W1_F4 (DIM_D * DIM_H / 4)
#define W2_F4 (DIM_H * DIM_DOUT / 4)
#define A_F4  (MSP_PAD * DIM_D / 4)

__global__ __launch_bounds__(256) void conv_kernel(
    const float* __restrict__ W1,
    const float* __restrict__ slots,
    const float* __restrict__ pos)
{
    int i = blockIdx.x * 256 + threadIdx.x;
    if (i < W1_F4) {
        *(uint2*)&g_W1h[i * 4] = f4_to_h4(*(const float4*)&W1[i * 4]);
    } else if (i < W1_F4 + A_F4) {
        int j = i - W1_F4;
        int m = (j * 4) / DIM_D;
        int c = (j * 4) % DIM_D;
        float4 v = make_float4(0.f, 0.f, 0.f, 0.f);
        if (m < 128)      v = *(const float4*)&slots[m * DIM_D + c];
        else if (m < MSP) v = *(const float4*)&pos[(m - 128) * DIM_D + c];
        *(uint2*)&g_Ah[j * 4] = f4_to_h4(v);
    }
}

#define LDA 72     // halves (64 + 8 pad)
#define LDB 136    // halves (128 + 8 pad)
#define ASZ (64 * LDA)          // halves per A stage
#define BSZ (64 * LDB)          // halves per B stage

// ---------------------------------------------------------------------------
// Kernel 1: GEMM1  g_Ah(384x768) @ g_W1h(768x3072) -> g_SP1h (fp16)
// BM=64 BN=128 BK=64, 256 thr, warp 32x32, 4-stage pipeline. grid (24,6)
// Epilogue: acc -> smem fp32 -> fp16 global (halves write traffic).
// ---------------------------------------------------------------------------
#define G1_NSTG 4
#define G1_SMEM (G1_NSTG * (ASZ + BSZ) * 2)   // 106496

__global__ __launch_bounds__(256) void gemm_small_kernel()
{
    constexpr int KT  = DIM_D / 64;   // 12
    constexpr int LDC = 132;          // floats

    extern __shared__ __align__(16) char smraw[];
    __half* As = (__half*)smraw;
    __half* Bs = As + G1_NSTG * ASZ;
    float*  Cs = (float*)smraw;       // epilogue reuse: 64*132*4 = 33792 B
    const unsigned sb  = smem_u32(smraw);
    const unsigned sbB = sb + G1_NSTG * ASZ * 2;

    const int h0  = blockIdx.x * 128;
    const int m0  = blockIdx.y * 64;
    const int tid = threadIdx.x;
    const int wid = tid >> 5;
    const int warp_m = wid >> 2;
    const int warp_n = wid & 3;

    wmma::fragment<wmma::accumulator, 16, 16, 16, float> acc[2][2];
#pragma unroll
    for (int i = 0; i < 2; i++)
#pragma unroll
        for (int j = 0; j < 2; j++)
            wmma::fill_fragment(acc[i][j], 0.0f);

    const int ar = tid >> 2, ac = (tid & 3) * 8;
    const int br = tid >> 4, bc = (tid & 15) * 8;

    const __half* gA = g_Ah + (size_t)(m0 + ar) * DIM_D + ac;

#define LOAD1(kt, st)                                                             \
    {                                                                             \
        unsigned sA0 = sb + (st) * ASZ * 2;                                       \
        cp16u(sA0 + (ar * LDA + ac) * 2,        gA + (kt) * 64);                  \
        cp16u(sA0 + (ar * LDA + ac + 32) * 2,   gA + (kt) * 64 + 32);             \
        const __half* gB = g_W1h + (size_t)((kt) * 64 + br) * DIM_H + h0 + bc;    \
        unsigned sB0 = sbB + (st) * BSZ * 2;                                      \
        cp16u(sB0 + (br * LDB + bc) * 2,        gB);                              \
        cp16u(sB0 + ((br + 16) * LDB + bc) * 2, gB + (size_t)16 * DIM_H);         \
        cp16u(sB0 + ((br + 32) * LDB + bc) * 2, gB + (size_t)32 * DIM_H);         \
        cp16u(sB0 + ((br + 48) * LDB + bc) * 2, gB + (size_t)48 * DIM_H);         \
    }

#pragma unroll
    for (int p = 0; p < G1_NSTG - 1; p++) {
        LOAD1(p, p);
        asm volatile("cp.async.commit_group;");
    }

    for (int kt = 0; kt < KT; kt++) {
        asm volatile("cp.async.wait_group %0;" :: "n"(G1_NSTG - 2));
        __syncthreads();
        if (kt + G1_NSTG - 1 < KT) {
            LOAD1(kt + G1_NSTG - 1, (kt + G1_NSTG - 1) & (G1_NSTG - 1));
        }
        asm volatile("cp.async.commit_group;");
        const __half* sA = As + (kt & (G1_NSTG - 1)) * ASZ;
        const __half* sB = Bs + (kt & (G1_NSTG - 1)) * BSZ;
#pragma unroll
        for (int ks = 0; ks < 64; ks += 16) {
            wmma::fragment<wmma::matrix_a, 16, 16, 16, __half, wmma::row_major> af[2];
            wmma::fragment<wmma::matrix_b, 16, 16, 16, __half, wmma::row_major> bf[2];
#pragma unroll
            for (int i = 0; i < 2; i++)
                wmma::load_matrix_sync(af[i], &sA[(warp_m * 32 + i * 16) * LDA + ks], LDA);
#pragma unroll
            for (int j = 0; j < 2; j++)
                wmma::load_matrix_sync(bf[j], &sB[ks * LDB + warp_n * 32 + j * 16], LDB);
#pragma unroll
            for (int i = 0; i < 2; i++)
#pragma unroll
                for (int j = 0; j < 2; j++)
                    wmma::mma_sync(acc[i][j], af[i], bf[j], acc[i][j]);
        }
    }
#undef LOAD1

    // drain cp.async, then epilogue: acc -> smem fp32 -> fp16 global
    asm volatile("cp.async.wait_group 0;");
    __syncthreads();
#pragma unroll
    for (int i = 0; i < 2; i++)
#pragma unroll
        for (int j = 0; j < 2; j++)
            wmma::store_matrix_sync(
                &Cs[(warp_m * 32 + i * 16) * LDC + warp_n * 32 + j * 16],
                acc[i][j], LDC, wmma::mem_row_major);
    __syncthreads();

    // 64 rows x 32 float4 = 2048 slots -> 8 iterations
#pragma unroll
    for (int p = 0; p < 8; p++) {
        int o = p * 256 + tid;
        int r = o >> 5, c4 = (o & 31) * 4;
        float4 v = *(float4*)&Cs[r * LDC + c4];
        *(uint2*)&g_SP1h[(size_t)(m0 + r) * DIM_H + h0 + c4] = f4_to_h4(v);
    }
}

// ---------------------------------------------------------------------------
// Kernel 2: combine (z<16) + W2->fp16 conversion (z==16). grid (14,3,17)
// combine: Gh[b*196+n,h] = fp16( 0.125*sum_k relu(S1h[b,k,h]+P1h[n,h]+b1[h]) )
// S1h/P1h are fp16 (half the read traffic vs fp32).
// ---------------------------------------------------------------------------
__global__ __launch_bounds__(256) void combine_kernel(
    const float* __restrict__ b1,
    const float* __restrict__ W2)
{
    if (blockIdx.z == 16) {
        int base = (blockIdx.y * 14 + blockIdx.x) * 256 + threadIdx.x;
        for (int i = base; i < W2_F4; i += 42 * 256) {
            *(uint2*)&g_W2h[i * 4] = f4_to_h4(*(const float4*)&W2[i * 4]);
        }
        return;
    }

    const int b  = blockIdx.z;
    const int h0 = blockIdx.y * 1024 + threadIdx.x * 4;
    const int n0 = blockIdx.x * 14;

    float4 s[8];
#pragma unroll
    for (int k = 0; k < 8; k++)
        s[k] = h4_to_f4(*(const uint2*)&g_SP1h[(size_t)(b * 8 + k) * DIM_H + h0]);
    float4 bb = *(const float4*)&b1[h0];
#pragma unroll
    for (int k = 0; k < 8; k++) {
        s[k].x += bb.x; s[k].y += bb.y; s[k].z += bb.z; s[k].w += bb.w;
    }

#pragma unroll 2
    for (int n = 0; n < 14; n++) {
        int nn = n0 + n;
        float4 p = h4_to_f4(*(const uint2*)&g_SP1h[(size_t)(128 + nn) * DIM_H + h0]);
        float4 a;
        a.x = a.y = a.z = a.w = 0.0f;
#pragma unroll
        for (int k = 0; k < 8; k++) {
            a.x += fmaxf(s[k].x + p.x, 0.0f);
            a.y += fmaxf(s[k].y + p.y, 0.0f);
            a.z += fmaxf(s[k].z + p.z, 0.0f);
            a.w += fmaxf(s[k].w + p.w, 0.0f);
        }
        a.x *= 0.125f; a.y *= 0.125f; a.z *= 0.125f; a.w *= 0.125f;
        *(uint2*)&g_Gh[(size_t)(b * DIM_N + nn) * DIM_H + h0] = f4_to_h4(a);
    }
}

// ---------------------------------------------------------------------------
// Pass 2 (fp16): out(3136x768) = Gh(3136x3072) @ W2h(3072x768) + b2
// BM=64 BN=128 BK=64, 256 thr, warp 32x32, 4-stage pipeline, wait_group 2.
// grid (6,49)=294 CTAs, 2 CTAs/SM. (R14 config — at LTS-cap floor.)
// ---------------------------------------------------------------------------
#define P2_NSTG 4
#define P2_SMEM (P2_NSTG * (ASZ + BSZ) * 2)   // 106496

__global__ __launch_bounds__(256) void pass2_kernel(
    const float* __restrict__ b2,
    float* __restrict__ out)
{
    constexpr int KT  = DIM_H / 64;   // 48
    constexpr int LDC = 132;          // floats

    extern __shared__ __align__(16) char smraw[];
    __half* As = (__half*)smraw;          // P2_NSTG * ASZ
    __half* Bs = As + P2_NSTG * ASZ;      // P2_NSTG * BSZ
    float*  Cs = (float*)smraw;           // epilogue reuse: 64*132*4 = 33792 B

    const unsigned sb  = smem_u32(smraw);
    const unsigned sbB = sb + P2_NSTG * ASZ * 2;

    const int o0  = blockIdx.x * 128;
    const int m0  = blockIdx.y * 64;
    const int tid = threadIdx.x;
    const int wid = tid >> 5;
    const int warp_m = wid >> 2;
    const int warp_n = wid & 3;

    wmma::fragment<wmma::accumulator, 16, 16, 16, float> acc[2][2];
#pragma unroll
    for (int i = 0; i < 2; i++)
#pragma unroll
        for (int j = 0; j < 2; j++)
            wmma::fill_fragment(acc[i][j], 0.0f);

    const int ar = tid >> 2, ac = (tid & 3) * 8;
    const int br = tid >> 4, bc = (tid & 15) * 8;

    const __half* gA = g_Gh + (size_t)(m0 + ar) * DIM_H + ac;

#define LOAD2(kt, st)                                                             \
    {                                                                             \
        unsigned sA0 = sb + (st) * ASZ * 2;                                       \
        cp16u(sA0 + (ar * LDA + ac) * 2,        gA + (kt) * 64);                  \
        cp16u(sA0 + (ar * LDA + ac + 32) * 2,   gA + (kt) * 64 + 32);             \
        const __half* gB = g_W2h + (size_t)((kt) * 64 + br) * DIM_DOUT + o0 + bc; \
        unsigned sB0 = sbB + (st) * BSZ * 2;                                      \
        cp16u(sB0 + (br * LDB + bc) * 2,        gB);                              \
        cp16u(sB0 + ((br + 16) * LDB + bc) * 2, gB + 16 * DIM_DOUT);              \
        cp16u(sB0 + ((br + 32) * LDB + bc) * 2, gB + 32 * DIM_DOUT);              \
        cp16u(sB0 + ((br + 48) * LDB + bc) * 2, gB + 48 * DIM_DOUT);              \
    }

#pragma unroll
    for (int p = 0; p < P2_NSTG - 1; p++) {
        LOAD2(p, p);
        asm volatile("cp.async.commit_group;");
    }

    for (int kt = 0; kt < KT; kt++) {
        asm volatile("cp.async.wait_group %0;" :: "n"(P2_NSTG - 2));
        __syncthreads();
        if (kt + P2_NSTG - 1 < KT) {
            LOAD2(kt + P2_NSTG - 1, (kt + P2_NSTG - 1) & (P2_NSTG - 1));
        }
        asm volatile("cp.async.commit_group;");
        const __half* sA = As + (kt & (P2_NSTG - 1)) * ASZ;
        const __half* sB = Bs + (kt & (P2_NSTG - 1)) * BSZ;
#pragma unroll
        for (int ks = 0; ks < 64; ks += 16) {
            wmma::fragment<wmma::matrix_a, 16, 16, 16, __half, wmma::row_major> af[2];
            wmma::fragment<wmma::matrix_b, 16, 16, 16, __half, wmma::row_major> bf[2];
#pragma unroll
            for (int i = 0; i < 2; i++)
                wmma::load_matrix_sync(af[i], &sA[(warp_m * 32 + i * 16) * LDA + ks], LDA);
#pragma unroll
            for (int j = 0; j < 2; j++)
                wmma::load_matrix_sync(bf[j], &sB[ks * LDB + warp_n * 32 + j * 16], LDB);
#pragma unroll
            for (int i = 0; i < 2; i++)
#pragma unroll
                for (int j = 0; j < 2; j++)
                    wmma::mma_sync(acc[i][j], af[i], bf[j], acc[i][j]);
        }
    }
#undef LOAD2

    // drain + epilogue via smem (reuses tile space), add bias, write out
    asm volatile("cp.async.wait_group 0;");
    __syncthreads();
#pragma unroll
    for (int i = 0; i < 2; i++)
#pragma unroll
        for (int j = 0; j < 2; j++)
            wmma::store_matrix_sync(
                &Cs[(warp_m * 32 + i * 16) * LDC + warp_n * 32 + j * 16],
                acc[i][j], LDC, wmma::mem_row_major);
    __syncthreads();

#pragma unroll
    for (int p = 0; p < 8; p++) {
        int o = p * 256 + tid;
        int r = o >> 5, c4 = (o & 31) * 4;
        float4 v = *(float4*)&Cs[r * LDC + c4];
        float4 bb = *(const float4*)&b2[o0 + c4];
        v.x += bb.x; v.y += bb.y; v.z += bb.z; v.w += bb.w;
        *(float4*)&out[(size_t)(m0 + r) * DIM_DOUT + o0 + c4] = v;
    }
}

// ---------------------------------------------------------------------------
extern "C" void kernel_launch(void* const* d_in, const int* in_sizes, int n_in,
                              void* d_out, int out_size)
{
    const float* slots = (const float*)d_in[0];   // (16,8,768)
    const float* pos   = (const float*)d_in[1];   // (196,768)
    // d_in[2] = map_alpha : softmax over K of identical values == 1/8 exactly
    const float* W1    = (const float*)d_in[3];   // (768,3072)
    const float* b1    = (const float*)d_in[4];   // (3072,)
    const float* W2    = (const float*)d_in[5];   // (3072,768)
    const float* b2    = (const float*)d_in[6];   // (768,)
    float* out = (float*)d_out;                   // (16,196,768)

    cudaFuncSetAttribute(gemm_small_kernel,
                         cudaFuncAttributeMaxDynamicSharedMemorySize, G1_SMEM);
    cudaFuncSetAttribute(pass2_kernel,
                         cudaFuncAttributeMaxDynamicSharedMemorySize, P2_SMEM);

    constexpr int CONV_BLKS = (W1_F4 + A_F4 + 255) / 256;
    conv_kernel<<<CONV_BLKS, 256>>>(W1, slots, pos);

    dim3 gs(DIM_H / 128, MSP_PAD / 64);             // (24, 6)
    gemm_small_kernel<<<gs, 256, G1_SMEM>>>();

    dim3 gc(14, 3, 17);                             // combine + W2 conversion
    combine_kernel<<<gc, 256>>>(b1, W2);

    dim3 g2(DIM_DOUT / 128, M2 / 64);               // (6, 49) = 294 blocks
    pass2_kernel<<<g2, 256, P2_SMEM>>>(b2, out);
}